// round 5
// baseline (speedup 1.0000x reference)
#include <cuda_runtime.h>
#include <cstdint>

// Problem constants
#define NN 150000     // N = U + I
#define UU 100000
#define II 50000
#define RR 5
#define LLAYERS 3
#define EE 500000
#define BB 8192
#define SLOPEF 0.01f

// Scratch (device globals; allocation-free per harness rules).
// Single-rating g_h keeps the scatter's gather source L2-resident
// (h + agg + x = 114 MB < 126 MB L2).
__device__ float4 g_x[NN * 16];    // current layer input  [N,64]
__device__ float4 g_acc[NN * 16];  // running sum [N,64]
__device__ float4 g_h[NN * 16];    // current-rating transformed features [N,64]
__device__ float4 g_agg[NN * 16];  // sum over ratings of scattered messages [N,64]
__device__ float  g_c[RR * 64];    // per-rating bias: re @ aw1[:,D:,:] + ab1

// ---- packed f32x2 helpers (Blackwell FFMA2 path, PTX-only) -----------------
__device__ __forceinline__ void fma2(uint64_t& acc, uint64_t a, uint64_t b)
{
    asm("fma.rn.f32x2 %0, %1, %2, %0;" : "+l"(acc) : "l"(a), "l"(b));
}
__device__ __forceinline__ uint64_t pack2(float lo, float hi)
{
    uint64_t r;
    asm("mov.b64 %0, {%1, %2};" : "=l"(r) : "f"(lo), "f"(hi));
    return r;
}
__device__ __forceinline__ void unpack2(uint64_t v, float& lo, float& hi)
{
    asm("mov.b64 {%0, %1}, %2;" : "=f"(lo), "=f"(hi) : "l"(v));
}

// ---------------------------------------------------------------------------
// init: x = concat(user_emb, item_emb); acc = x; agg = 0
// ---------------------------------------------------------------------------
__global__ void init_kernel(const float4* __restrict__ ue, const float4* __restrict__ ie)
{
    int i = blockIdx.x * blockDim.x + threadIdx.x;
    if (i >= NN * 16) return;
    float4 v = (i < UU * 16) ? ue[i] : ie[i - UU * 16];
    g_x[i] = v;
    g_acc[i] = v;
    g_agg[i] = make_float4(0.f, 0.f, 0.f, 0.f);
}

// ---------------------------------------------------------------------------
// c[r,k] = ab1[r,k] + sum_d rating_emb[1+r,d] * aw1[r, 64+d, k]
// ---------------------------------------------------------------------------
__global__ void cbias_kernel(const float* __restrict__ rating_emb,
                             const float* __restrict__ aw1,
                             const float* __restrict__ ab1)
{
    int r = blockIdx.x;
    int k = threadIdx.x;
    const float* re = rating_emb + (1 + r) * 64;
    const float* w  = aw1 + r * 128 * 64 + 64 * 64;  // rows D..2D-1
    float s = ab1[r * 64 + k];
    #pragma unroll
    for (int d = 0; d < 64; d++) s += re[d] * w[d * 64 + k];
    g_c[r * 64 + k] = s;
}

// ---------------------------------------------------------------------------
// Per-node fused 2-layer transform for one rating r, FFMA2 (f32x2) mainloops:
//   h = (leaky(x @ W1_r + c_r)) @ W2_r + ab2_r  ->  g_h
// One node per thread; accumulators as packed b64 pairs; weights read from
// 16B-ALIGNED smem as ulonglong2 (LDS.128 -> two b64 operands, no repacking).
// ---------------------------------------------------------------------------
__global__ __launch_bounds__(128) void node_mlp_kernel(
    int r,
    const float* __restrict__ aw1,   // [R,128,64]
    const float* __restrict__ aw2,   // [R,64,64]
    const float* __restrict__ ab2)   // [R,64]
{
    __shared__ __align__(16) float sW1[64 * 64];
    __shared__ __align__(16) float sW2[64 * 64];
    __shared__ float sc[64];
    __shared__ float sb[64];

    const float* W1 = aw1 + r * 128 * 64;   // first 64 rows used
    const float* W2 = aw2 + r * 64 * 64;
    int tid = threadIdx.x;
    #pragma unroll
    for (int i = 0; i < 32; i++) {
        sW1[tid + 128 * i] = W1[tid + 128 * i];
        sW2[tid + 128 * i] = W2[tid + 128 * i];
    }
    if (tid < 64) { sc[tid] = g_c[r * 64 + tid]; sb[tid] = ab2[r * 64 + tid]; }
    __syncthreads();

    int n = blockIdx.x * 128 + tid;
    if (n >= NN) return;

    // load x row into registers
    float xr[64];
    const float4* xp = g_x + (size_t)n * 16;
    #pragma unroll
    for (int i = 0; i < 16; i++) {
        float4 v = xp[i];
        xr[4*i+0] = v.x; xr[4*i+1] = v.y; xr[4*i+2] = v.z; xr[4*i+3] = v.w;
    }

    // stage 1: h1 = leaky(x @ W1 + c)     [32 packed pair accumulators]
    uint64_t h1p[32];
    #pragma unroll
    for (int k = 0; k < 32; k++) h1p[k] = pack2(sc[2*k], sc[2*k+1]);
    #pragma unroll
    for (int d = 0; d < 64; d++) {
        uint64_t xd2 = pack2(xr[d], xr[d]);
        const ulonglong2* w = (const ulonglong2*)(sW1 + d * 64);
        #pragma unroll
        for (int k = 0; k < 16; k++) {
            ulonglong2 wv = w[k];
            fma2(h1p[2*k+0], xd2, wv.x);
            fma2(h1p[2*k+1], xd2, wv.y);
        }
    }
    // leaky(x) = max(x, SLOPE*x) (valid for both signs since 0 < SLOPE < 1)
    float h1[64];
    #pragma unroll
    for (int k = 0; k < 32; k++) {
        float a, b;
        unpack2(h1p[k], a, b);
        h1[2*k+0] = fmaxf(a, SLOPEF * a);
        h1[2*k+1] = fmaxf(b, SLOPEF * b);
    }

    // stage 2: o = h1 @ W2 + ab2   (xr dead; op reuses registers)
    uint64_t op[32];
    #pragma unroll
    for (int m = 0; m < 32; m++) op[m] = pack2(sb[2*m], sb[2*m+1]);
    #pragma unroll
    for (int k = 0; k < 64; k++) {
        uint64_t hk2 = pack2(h1[k], h1[k]);
        const ulonglong2* w = (const ulonglong2*)(sW2 + k * 64);
        #pragma unroll
        for (int m = 0; m < 16; m++) {
            ulonglong2 wv = w[m];
            fma2(op[2*m+0], hk2, wv.x);
            fma2(op[2*m+1], hk2, wv.y);
        }
    }

    // store: packed pairs are bit-identical to float4 lanes (16B-aligned global)
    ulonglong2* hp = (ulonglong2*)(g_h + (size_t)n * 16);
    #pragma unroll
    for (int i = 0; i < 16; i++) {
        ulonglong2 v;
        v.x = op[2*i+0];
        v.y = op[2*i+1];
        hp[i] = v;
    }
}

// ---------------------------------------------------------------------------
// Edge scatter for one rating: agg[row] += val * h[col]
// 16 threads per edge, float4 each; no-return vector reduction (REDG path).
// h is L2-hot (just written by node_mlp for this rating). g_agg is float4 ->
// 16B-aligned, satisfying red .v4 alignment.
// ---------------------------------------------------------------------------
__global__ void scatter_kernel(const int* __restrict__ rows,
                               const int* __restrict__ cols,
                               const float* __restrict__ vals)
{
    int idx = blockIdx.x * blockDim.x + threadIdx.x;
    int e = idx >> 4;
    if (e >= EE) return;
    int j = idx & 15;
    int row = rows[e];
    int col = cols[e];
    float v = vals[e];
    float4 hv = *(const float4*)(g_h + (size_t)col * 16 + j);
    float4* dst = g_agg + (size_t)row * 16 + j;
    asm volatile("red.global.add.v4.f32 [%0], {%1, %2, %3, %4};"
                 :: "l"(dst), "f"(v * hv.x), "f"(v * hv.y),
                    "f"(v * hv.z), "f"(v * hv.w)
                 : "memory");
}

// ---------------------------------------------------------------------------
// x = agg / R; acc += x; agg = 0 (ready for next layer)
// ---------------------------------------------------------------------------
__global__ void update_kernel()
{
    int i = blockIdx.x * blockDim.x + threadIdx.x;
    if (i >= NN * 16) return;
    float4 a = g_agg[i];
    float4 x = make_float4(a.x * 0.2f, a.y * 0.2f, a.z * 0.2f, a.w * 0.2f);
    g_x[i] = x;
    float4 ac = g_acc[i];
    ac.x += x.x; ac.y += x.y; ac.z += x.z; ac.w += x.w;
    g_acc[i] = ac;
    g_agg[i] = make_float4(0.f, 0.f, 0.f, 0.f);
}

// ---------------------------------------------------------------------------
// Final: gather (u, pos/neg item), light = acc/(L+1), 3-layer prediction MLP.
// One sample per thread; out[0..B) = pred, out[B..2B) = neg_pred.
// ---------------------------------------------------------------------------
__global__ __launch_bounds__(128) void predict_kernel(
    const int* __restrict__ users, const int* __restrict__ pos, const int* __restrict__ neg,
    const float* __restrict__ pw1, const float* __restrict__ pb1,
    const float* __restrict__ pw2, const float* __restrict__ pb2,
    const float* __restrict__ pw3, const float* __restrict__ pb3,
    float* __restrict__ out)
{
    __shared__ __align__(16) float s1[128 * 64];   // 32 KB
    __shared__ __align__(16) float s2[64 * 32];    // 8 KB
    __shared__ float s3[32];
    __shared__ float sb1[64];
    __shared__ float sb2[32];
    __shared__ float sb3;

    int tid = threadIdx.x;
    for (int i = tid; i < 128 * 64; i += 128) s1[i] = pw1[i];
    for (int i = tid; i < 64 * 32; i += 128)  s2[i] = pw2[i];
    if (tid < 32) { s3[tid] = pw3[tid]; sb2[tid] = pb2[tid]; }
    if (tid < 64) sb1[tid] = pb1[tid];
    if (tid == 0) sb3 = pb3[0];
    __syncthreads();

    int s = blockIdx.x * 128 + tid;
    if (s >= 2 * BB) return;
    int q  = (s < BB) ? s : s - BB;
    int u  = users[q];
    int it = (s < BB) ? pos[q] : neg[q];

    const float* urow = (const float*)g_acc + (size_t)u * 64;
    const float* prow = (const float*)g_acc + (size_t)(UU + it) * 64;
    const float inv = 1.0f / (LLAYERS + 1);

    // h1 = leaky([u,p] @ pw1 + pb1), packed accumulators
    uint64_t h1p[32];
    #pragma unroll
    for (int k = 0; k < 32; k++) h1p[k] = pack2(sb1[2*k], sb1[2*k+1]);
    for (int d = 0; d < 64; d++) {
        float fd = inv * urow[d];
        uint64_t fd2 = pack2(fd, fd);
        const ulonglong2* w = (const ulonglong2*)(s1 + d * 64);
        #pragma unroll
        for (int k = 0; k < 16; k++) {
            ulonglong2 wv = w[k];
            fma2(h1p[2*k+0], fd2, wv.x);
            fma2(h1p[2*k+1], fd2, wv.y);
        }
    }
    for (int d = 0; d < 64; d++) {
        float fd = inv * prow[d];
        uint64_t fd2 = pack2(fd, fd);
        const ulonglong2* w = (const ulonglong2*)(s1 + (64 + d) * 64);
        #pragma unroll
        for (int k = 0; k < 16; k++) {
            ulonglong2 wv = w[k];
            fma2(h1p[2*k+0], fd2, wv.x);
            fma2(h1p[2*k+1], fd2, wv.y);
        }
    }
    float h1[64];
    #pragma unroll
    for (int k = 0; k < 32; k++) {
        float a, b;
        unpack2(h1p[k], a, b);
        h1[2*k+0] = fmaxf(a, SLOPEF * a);
        h1[2*k+1] = fmaxf(b, SLOPEF * b);
    }

    float h2[32];
    #pragma unroll
    for (int m = 0; m < 32; m++) h2[m] = sb2[m];
    for (int k = 0; k < 64; k++) {
        float hk = h1[k];
        const float4* w = (const float4*)(s2 + k * 32);
        #pragma unroll
        for (int m = 0; m < 8; m++) {
            float4 wv = w[m];
            h2[4*m+0] += hk * wv.x; h2[4*m+1] += hk * wv.y;
            h2[4*m+2] += hk * wv.z; h2[4*m+3] += hk * wv.w;
        }
    }
    float o = sb3;
    #pragma unroll
    for (int m = 0; m < 32; m++) {
        float hm = fmaxf(h2[m], SLOPEF * h2[m]);
        o += hm * s3[m];
    }
    out[s] = o;
}

// ---------------------------------------------------------------------------
// launch
// ---------------------------------------------------------------------------
extern "C" void kernel_launch(void* const* d_in, const int* in_sizes, int n_in,
                              void* d_out, int out_size)
{
    const int*   users      = (const int*)d_in[0];
    const int*   pos_items  = (const int*)d_in[1];
    const int*   neg_items  = (const int*)d_in[2];
    const float* user_emb   = (const float*)d_in[3];
    const float* item_emb   = (const float*)d_in[4];
    const float* rating_emb = (const float*)d_in[5];
    const float* aw1        = (const float*)d_in[6];
    const float* ab1        = (const float*)d_in[7];
    const float* aw2        = (const float*)d_in[8];
    const float* ab2        = (const float*)d_in[9];
    const float* pw1        = (const float*)d_in[10];
    const float* pb1        = (const float*)d_in[11];
    const float* pw2        = (const float*)d_in[12];
    const float* pb2        = (const float*)d_in[13];
    const float* pw3        = (const float*)d_in[14];
    const float* pb3        = (const float*)d_in[15];
    const int*   erows      = (const int*)d_in[16];
    const int*   ecols      = (const int*)d_in[17];
    const float* evals      = (const float*)d_in[18];
    float* out = (float*)d_out;

    init_kernel<<<(NN * 16 + 255) / 256, 256>>>((const float4*)user_emb,
                                                (const float4*)item_emb);
    cbias_kernel<<<RR, 64>>>(rating_emb, aw1, ab1);

    const int mlp_blocks = (NN + 127) / 128;
    const int sc_blocks  = (EE * 16 + 255) / 256;

    for (int l = 0; l < LLAYERS; l++) {
        for (int r = 0; r < RR; r++) {
            node_mlp_kernel<<<mlp_blocks, 128>>>(r, aw1, aw2, ab2);
            scatter_kernel<<<sc_blocks, 256>>>(erows + (size_t)r * EE,
                                               ecols + (size_t)r * EE,
                                               evals + (size_t)r * EE);
        }
        update_kernel<<<(NN * 16 + 255) / 256, 256>>>();
    }

    predict_kernel<<<(2 * BB + 127) / 128, 128>>>(users, pos_items, neg_items,
                                                  pw1, pb1, pw2, pb2, pw3, pb3, out);
}

// round 6
// speedup vs baseline: 1.0160x; 1.0160x over previous
#include <cuda_runtime.h>
#include <cstdint>

// Problem constants
#define NN 150000     // N = U + I
#define UU 100000
#define II 50000
#define RR 5
#define LLAYERS 3
#define EE 500000
#define BB 8192
#define SLOPEF 0.01f

// Scratch (device globals; allocation-free per harness rules).
// g_h2 is double-buffered so node_mlp(r+1) can run concurrently with
// scatter(r) on a second stream.
__device__ float4 g_x[NN * 16];        // current layer input  [N,64]
__device__ float4 g_acc[NN * 16];      // running sum [N,64]
__device__ float4 g_h2[2][NN * 16];    // double-buffered transformed features
__device__ float4 g_agg[NN * 16];      // sum over ratings of scattered messages
__device__ float  g_c[RR * 64];        // per-rating bias: re @ aw1[:,D:,:] + ab1

// ---- packed f32x2 helpers (Blackwell FFMA2 path, PTX-only) -----------------
__device__ __forceinline__ void fma2(uint64_t& acc, uint64_t a, uint64_t b)
{
    asm("fma.rn.f32x2 %0, %1, %2, %0;" : "+l"(acc) : "l"(a), "l"(b));
}
__device__ __forceinline__ uint64_t pack2(float lo, float hi)
{
    uint64_t r;
    asm("mov.b64 %0, {%1, %2};" : "=l"(r) : "f"(lo), "f"(hi));
    return r;
}
__device__ __forceinline__ void unpack2(uint64_t v, float& lo, float& hi)
{
    asm("mov.b64 {%0, %1}, %2;" : "=f"(lo), "=f"(hi) : "l"(v));
}

// ---------------------------------------------------------------------------
// init: x = concat(user_emb, item_emb); acc = x; agg = 0
// ---------------------------------------------------------------------------
__global__ void init_kernel(const float4* __restrict__ ue, const float4* __restrict__ ie)
{
    int i = blockIdx.x * blockDim.x + threadIdx.x;
    if (i >= NN * 16) return;
    float4 v = (i < UU * 16) ? ue[i] : ie[i - UU * 16];
    g_x[i] = v;
    g_acc[i] = v;
    g_agg[i] = make_float4(0.f, 0.f, 0.f, 0.f);
}

// ---------------------------------------------------------------------------
// c[r,k] = ab1[r,k] + sum_d rating_emb[1+r,d] * aw1[r, 64+d, k]
// ---------------------------------------------------------------------------
__global__ void cbias_kernel(const float* __restrict__ rating_emb,
                             const float* __restrict__ aw1,
                             const float* __restrict__ ab1)
{
    int r = blockIdx.x;
    int k = threadIdx.x;
    const float* re = rating_emb + (1 + r) * 64;
    const float* w  = aw1 + r * 128 * 64 + 64 * 64;  // rows D..2D-1
    float s = ab1[r * 64 + k];
    #pragma unroll
    for (int d = 0; d < 64; d++) s += re[d] * w[d * 64 + k];
    g_c[r * 64 + k] = s;
}

// ---------------------------------------------------------------------------
// Per-node fused 2-layer transform for one rating r, FFMA2 (f32x2) mainloops:
//   h = (leaky(x @ W1_r + c_r)) @ W2_r + ab2_r  ->  g_h2[buf]
// ---------------------------------------------------------------------------
__global__ __launch_bounds__(128) void node_mlp_kernel(
    int r, int buf,
    const float* __restrict__ aw1,   // [R,128,64]
    const float* __restrict__ aw2,   // [R,64,64]
    const float* __restrict__ ab2)   // [R,64]
{
    __shared__ __align__(16) float sW1[64 * 64];
    __shared__ __align__(16) float sW2[64 * 64];
    __shared__ float sc[64];
    __shared__ float sb[64];

    const float* W1 = aw1 + r * 128 * 64;   // first 64 rows used
    const float* W2 = aw2 + r * 64 * 64;
    int tid = threadIdx.x;
    #pragma unroll
    for (int i = 0; i < 32; i++) {
        sW1[tid + 128 * i] = W1[tid + 128 * i];
        sW2[tid + 128 * i] = W2[tid + 128 * i];
    }
    if (tid < 64) { sc[tid] = g_c[r * 64 + tid]; sb[tid] = ab2[r * 64 + tid]; }
    __syncthreads();

    int n = blockIdx.x * 128 + tid;
    if (n >= NN) return;

    // load x row into registers
    float xr[64];
    const float4* xp = g_x + (size_t)n * 16;
    #pragma unroll
    for (int i = 0; i < 16; i++) {
        float4 v = xp[i];
        xr[4*i+0] = v.x; xr[4*i+1] = v.y; xr[4*i+2] = v.z; xr[4*i+3] = v.w;
    }

    // stage 1: h1 = leaky(x @ W1 + c)     [32 packed pair accumulators]
    uint64_t h1p[32];
    #pragma unroll
    for (int k = 0; k < 32; k++) h1p[k] = pack2(sc[2*k], sc[2*k+1]);
    #pragma unroll
    for (int d = 0; d < 64; d++) {
        uint64_t xd2 = pack2(xr[d], xr[d]);
        const ulonglong2* w = (const ulonglong2*)(sW1 + d * 64);
        #pragma unroll
        for (int k = 0; k < 16; k++) {
            ulonglong2 wv = w[k];
            fma2(h1p[2*k+0], xd2, wv.x);
            fma2(h1p[2*k+1], xd2, wv.y);
        }
    }
    // leaky(x) = max(x, SLOPE*x) (valid for both signs since 0 < SLOPE < 1)
    float h1[64];
    #pragma unroll
    for (int k = 0; k < 32; k++) {
        float a, b;
        unpack2(h1p[k], a, b);
        h1[2*k+0] = fmaxf(a, SLOPEF * a);
        h1[2*k+1] = fmaxf(b, SLOPEF * b);
    }

    // stage 2: o = h1 @ W2 + ab2   (xr dead; op reuses registers)
    uint64_t op[32];
    #pragma unroll
    for (int m = 0; m < 32; m++) op[m] = pack2(sb[2*m], sb[2*m+1]);
    #pragma unroll
    for (int k = 0; k < 64; k++) {
        uint64_t hk2 = pack2(h1[k], h1[k]);
        const ulonglong2* w = (const ulonglong2*)(sW2 + k * 64);
        #pragma unroll
        for (int m = 0; m < 16; m++) {
            ulonglong2 wv = w[m];
            fma2(op[2*m+0], hk2, wv.x);
            fma2(op[2*m+1], hk2, wv.y);
        }
    }

    // store packed pairs (bit-identical to float4 lanes; 16B-aligned global)
    ulonglong2* hp = (ulonglong2*)(g_h2[buf] + (size_t)n * 16);
    #pragma unroll
    for (int i = 0; i < 16; i++) {
        ulonglong2 v;
        v.x = op[2*i+0];
        v.y = op[2*i+1];
        hp[i] = v;
    }
}

// ---------------------------------------------------------------------------
// Edge scatter for one rating: agg[row] += val * h[col]
// 16 threads per edge, float4 each; no-return vector reduction (REDG path).
// ---------------------------------------------------------------------------
__global__ void scatter_kernel(int buf,
                               const int* __restrict__ rows,
                               const int* __restrict__ cols,
                               const float* __restrict__ vals)
{
    int idx = blockIdx.x * blockDim.x + threadIdx.x;
    int e = idx >> 4;
    if (e >= EE) return;
    int j = idx & 15;
    int row = rows[e];
    int col = cols[e];
    float v = vals[e];
    float4 hv = *(const float4*)(g_h2[buf] + (size_t)col * 16 + j);
    float4* dst = g_agg + (size_t)row * 16 + j;
    asm volatile("red.global.add.v4.f32 [%0], {%1, %2, %3, %4};"
                 :: "l"(dst), "f"(v * hv.x), "f"(v * hv.y),
                    "f"(v * hv.z), "f"(v * hv.w)
                 : "memory");
}

// ---------------------------------------------------------------------------
// x = agg / R; acc += x; agg = 0 (ready for next layer)
// ---------------------------------------------------------------------------
__global__ void update_kernel()
{
    int i = blockIdx.x * blockDim.x + threadIdx.x;
    if (i >= NN * 16) return;
    float4 a = g_agg[i];
    float4 x = make_float4(a.x * 0.2f, a.y * 0.2f, a.z * 0.2f, a.w * 0.2f);
    g_x[i] = x;
    float4 ac = g_acc[i];
    ac.x += x.x; ac.y += x.y; ac.z += x.z; ac.w += x.w;
    g_acc[i] = ac;
    g_agg[i] = make_float4(0.f, 0.f, 0.f, 0.f);
}

// ---------------------------------------------------------------------------
// Final: gather (u, pos/neg item), light = acc/(L+1), 3-layer prediction MLP.
// ---------------------------------------------------------------------------
__global__ __launch_bounds__(128) void predict_kernel(
    const int* __restrict__ users, const int* __restrict__ pos, const int* __restrict__ neg,
    const float* __restrict__ pw1, const float* __restrict__ pb1,
    const float* __restrict__ pw2, const float* __restrict__ pb2,
    const float* __restrict__ pw3, const float* __restrict__ pb3,
    float* __restrict__ out)
{
    __shared__ __align__(16) float s1[128 * 64];   // 32 KB
    __shared__ __align__(16) float s2[64 * 32];    // 8 KB
    __shared__ float s3[32];
    __shared__ float sb1[64];
    __shared__ float sb2[32];
    __shared__ float sb3;

    int tid = threadIdx.x;
    for (int i = tid; i < 128 * 64; i += 128) s1[i] = pw1[i];
    for (int i = tid; i < 64 * 32; i += 128)  s2[i] = pw2[i];
    if (tid < 32) { s3[tid] = pw3[tid]; sb2[tid] = pb2[tid]; }
    if (tid < 64) sb1[tid] = pb1[tid];
    if (tid == 0) sb3 = pb3[0];
    __syncthreads();

    int s = blockIdx.x * 128 + tid;
    if (s >= 2 * BB) return;
    int q  = (s < BB) ? s : s - BB;
    int u  = users[q];
    int it = (s < BB) ? pos[q] : neg[q];

    const float* urow = (const float*)g_acc + (size_t)u * 64;
    const float* prow = (const float*)g_acc + (size_t)(UU + it) * 64;
    const float inv = 1.0f / (LLAYERS + 1);

    uint64_t h1p[32];
    #pragma unroll
    for (int k = 0; k < 32; k++) h1p[k] = pack2(sb1[2*k], sb1[2*k+1]);
    for (int d = 0; d < 64; d++) {
        float fd = inv * urow[d];
        uint64_t fd2 = pack2(fd, fd);
        const ulonglong2* w = (const ulonglong2*)(s1 + d * 64);
        #pragma unroll
        for (int k = 0; k < 16; k++) {
            ulonglong2 wv = w[k];
            fma2(h1p[2*k+0], fd2, wv.x);
            fma2(h1p[2*k+1], fd2, wv.y);
        }
    }
    for (int d = 0; d < 64; d++) {
        float fd = inv * prow[d];
        uint64_t fd2 = pack2(fd, fd);
        const ulonglong2* w = (const ulonglong2*)(s1 + (64 + d) * 64);
        #pragma unroll
        for (int k = 0; k < 16; k++) {
            ulonglong2 wv = w[k];
            fma2(h1p[2*k+0], fd2, wv.x);
            fma2(h1p[2*k+1], fd2, wv.y);
        }
    }
    float h1[64];
    #pragma unroll
    for (int k = 0; k < 32; k++) {
        float a, b;
        unpack2(h1p[k], a, b);
        h1[2*k+0] = fmaxf(a, SLOPEF * a);
        h1[2*k+1] = fmaxf(b, SLOPEF * b);
    }

    float h2[32];
    #pragma unroll
    for (int m = 0; m < 32; m++) h2[m] = sb2[m];
    for (int k = 0; k < 64; k++) {
        float hk = h1[k];
        const float4* w = (const float4*)(s2 + k * 32);
        #pragma unroll
        for (int m = 0; m < 8; m++) {
            float4 wv = w[m];
            h2[4*m+0] += hk * wv.x; h2[4*m+1] += hk * wv.y;
            h2[4*m+2] += hk * wv.z; h2[4*m+3] += hk * wv.w;
        }
    }
    float o = sb3;
    #pragma unroll
    for (int m = 0; m < 32; m++) {
        float hm = fmaxf(h2[m], SLOPEF * h2[m]);
        o += hm * s3[m];
    }
    out[s] = o;
}

// ---------------------------------------------------------------------------
// launch — two-stream software pipeline:
//   stream 0 (capture stream): init, cbias, all node_mlp, update, predict
//   stream s1:                 scatters, each gated on its mlp's event
// Double-buffered g_h2 lets mlp(t) overlap scatter(t-1); mlp(t) waits on
// scatter(t-2) (buffer reuse). update waits the layer's last scatter, which
// (scatters being ordered on s1) implies all five — rejoining the fork.
// ---------------------------------------------------------------------------
extern "C" void kernel_launch(void* const* d_in, const int* in_sizes, int n_in,
                              void* d_out, int out_size)
{
    const int*   users      = (const int*)d_in[0];
    const int*   pos_items  = (const int*)d_in[1];
    const int*   neg_items  = (const int*)d_in[2];
    const float* user_emb   = (const float*)d_in[3];
    const float* item_emb   = (const float*)d_in[4];
    const float* rating_emb = (const float*)d_in[5];
    const float* aw1        = (const float*)d_in[6];
    const float* ab1        = (const float*)d_in[7];
    const float* aw2        = (const float*)d_in[8];
    const float* ab2        = (const float*)d_in[9];
    const float* pw1        = (const float*)d_in[10];
    const float* pb1        = (const float*)d_in[11];
    const float* pw2        = (const float*)d_in[12];
    const float* pb2        = (const float*)d_in[13];
    const float* pw3        = (const float*)d_in[14];
    const float* pb3        = (const float*)d_in[15];
    const int*   erows      = (const int*)d_in[16];
    const int*   ecols      = (const int*)d_in[17];
    const float* evals      = (const float*)d_in[18];
    float* out = (float*)d_out;

    // One-time host-side stream/event setup (no device memory; work issued
    // per call is identical every call).
    static cudaStream_t s_side = nullptr;
    static cudaEvent_t  ev_mlp[LLAYERS * RR];
    static cudaEvent_t  ev_sc[LLAYERS * RR];
    if (s_side == nullptr) {
        cudaStreamCreateWithFlags(&s_side, cudaStreamNonBlocking);
        for (int i = 0; i < LLAYERS * RR; i++) {
            cudaEventCreateWithFlags(&ev_mlp[i], cudaEventDisableTiming);
            cudaEventCreateWithFlags(&ev_sc[i],  cudaEventDisableTiming);
        }
    }

    init_kernel<<<(NN * 16 + 255) / 256, 256>>>((const float4*)user_emb,
                                                (const float4*)item_emb);
    cbias_kernel<<<RR, 64>>>(rating_emb, aw1, ab1);

    const int mlp_blocks = (NN + 127) / 128;
    const int sc_blocks  = (EE * 16 + 255) / 256;

    int t = 0;
    for (int l = 0; l < LLAYERS; l++) {
        for (int r = 0; r < RR; r++, t++) {
            int buf = t & 1;
            if (t >= 2)  // h buffer reuse: prior reader must be done
                cudaStreamWaitEvent(0, ev_sc[t - 2], 0);
            node_mlp_kernel<<<mlp_blocks, 128, 0, 0>>>(r, buf, aw1, aw2, ab2);
            cudaEventRecord(ev_mlp[t], 0);

            cudaStreamWaitEvent(s_side, ev_mlp[t], 0);
            scatter_kernel<<<sc_blocks, 256, 0, s_side>>>(buf,
                                                          erows + (size_t)r * EE,
                                                          ecols + (size_t)r * EE,
                                                          evals + (size_t)r * EE);
            cudaEventRecord(ev_sc[t], s_side);
        }
        // join: all 5 scatters of this layer done before update
        cudaStreamWaitEvent(0, ev_sc[t - 1], 0);
        update_kernel<<<(NN * 16 + 255) / 256, 256>>>();
    }

    predict_kernel<<<(2 * BB + 127) / 128, 128>>>(users, pos_items, neg_items,
                                                  pw1, pb1, pw2, pb2, pw3, pb3, out);
}